// round 11
// baseline (speedup 1.0000x reference)
#include <cuda_runtime.h>
#include <cuda_bf16.h>

#define B_ 128
#define T_ 512
#define E_ 256
#define U_ 256

typedef unsigned long long u64t;

// 64MB scratch: xw[t][b][u]
__device__ __align__(16) float g_xw[T_ * B_ * U_];

__device__ __forceinline__ u64t ffma2(u64t a, u64t b, u64t c) {
    u64t d;
    asm("fma.rn.f32x2 %0, %1, %2, %3;" : "=l"(d) : "l"(a), "l"(b), "l"(c));
    return d;
}
__device__ __forceinline__ u64t addx2(u64t a, u64t b) {
    u64t d;
    asm("add.rn.f32x2 %0, %1, %2;" : "=l"(d) : "l"(a), "l"(b));
    return d;
}
__device__ __forceinline__ float f2lo(u64t v) { return __uint_as_float((unsigned)(v & 0xffffffffull)); }
__device__ __forceinline__ float f2hi(u64t v) { return __uint_as_float((unsigned)(v >> 32)); }
__device__ __forceinline__ float tanh_fast(float x) {
    float ex = __expf(2.0f * x);
    return 1.0f - __fdividef(2.0f, ex + 1.0f);
}

// ---------------- mbarrier / cluster helpers ----------------
__device__ __forceinline__ void mbar_init(unsigned addr, unsigned cnt) {
    asm volatile("mbarrier.init.shared.b64 [%0], %1;" :: "r"(addr), "r"(cnt) : "memory");
}
__device__ __forceinline__ void mbar_expect(unsigned addr, unsigned bytes) {
    asm volatile("mbarrier.arrive.expect_tx.shared.b64 _, [%0], %1;"
                 :: "r"(addr), "r"(bytes) : "memory");
}
__device__ __forceinline__ void mbar_wait(unsigned addr, unsigned parity) {
    unsigned done;
    asm volatile(
        "{\n\t.reg .pred p;\n\t"
        "mbarrier.try_wait.parity.acquire.cta.shared::cta.b64 p, [%1], %2;\n\t"
        "selp.b32 %0, 1, 0, p;\n\t}"
        : "=r"(done) : "r"(addr), "r"(parity) : "memory");
    if (!done) {
        asm volatile(
            "{\n\t.reg .pred P1;\n\t"
            "W_%=:\n\t"
            "mbarrier.try_wait.parity.acquire.cta.shared::cta.b64 P1, [%0], %1, 0x989680;\n\t"
            "@P1 bra D_%=;\n\t"
            "bra W_%=;\n\t"
            "D_%=:\n\t}"
            :: "r"(addr), "r"(parity) : "memory");
    }
}
__device__ __forceinline__ void st_async_f32(unsigned raddr, float v, unsigned rbar) {
    asm volatile("st.async.shared::cluster.mbarrier::complete_tx::bytes.b32 [%0], %1, [%2];"
                 :: "r"(raddr), "r"(__float_as_uint(v)), "r"(rbar) : "memory");
}
__device__ __forceinline__ void st_cluster_f32(unsigned raddr, float v) {
    asm volatile("st.shared::cluster.f32 [%0], %1;" :: "r"(raddr), "f"(v) : "memory");
}
__device__ __forceinline__ void cluster_sync_() {
    asm volatile("barrier.cluster.arrive.aligned;" ::: "memory");
    asm volatile("barrier.cluster.wait.aligned;" ::: "memory");
}

// ---------------------------------------------------------------------------
// Phase 1: xw[t][b][u] = sum_e emb[sentence[b][t]][e] * W[u][e]  (unchanged)
// ---------------------------------------------------------------------------
__global__ void __launch_bounds__(256)
xw_kernel(const int* __restrict__ sent, const float* __restrict__ emb,
          const float* __restrict__ Wm)
{
    __shared__ __align__(16) float2 As2[16 * 64];
    __shared__ __align__(16) float  Bs[16 * 256];
    __shared__ int idx[64];

    const int tid = threadIdx.x;
    const int r0 = blockIdx.x * 64;
    const int t  = r0 >> 7;
    const int b0 = r0 & 127;

    if (tid < 64) idx[tid] = sent[(b0 + tid) * T_ + t];
    __syncthreads();

    const int tx = tid & 15;
    const int ty = tid >> 4;
    const int arow = tid >> 2;
    const int aq = tid & 3;

    u64t acc[4][8];
    #pragma unroll
    for (int i = 0; i < 4; i++)
        #pragma unroll
        for (int p = 0; p < 8; p++) acc[i][p] = 0ull;

    float4 va = *(const float4*)(emb + (size_t)idx[arow] * E_ + aq * 4);
    float4 vb0 = *(const float4*)(Wm + (size_t)tid * E_ + 0);
    float4 vb1 = *(const float4*)(Wm + (size_t)tid * E_ + 4);
    float4 vb2 = *(const float4*)(Wm + (size_t)tid * E_ + 8);
    float4 vb3 = *(const float4*)(Wm + (size_t)tid * E_ + 12);

    for (int ko = 0; ko < 16; ko++) {
        if (ko > 0) __syncthreads();

        As2[(aq * 4 + 0) * 64 + arow] = make_float2(va.x, va.x);
        As2[(aq * 4 + 1) * 64 + arow] = make_float2(va.y, va.y);
        As2[(aq * 4 + 2) * 64 + arow] = make_float2(va.z, va.z);
        As2[(aq * 4 + 3) * 64 + arow] = make_float2(va.w, va.w);
        {
            const float v[16] = {vb0.x, vb0.y, vb0.z, vb0.w, vb1.x, vb1.y, vb1.z, vb1.w,
                                 vb2.x, vb2.y, vb2.z, vb2.w, vb3.x, vb3.y, vb3.z, vb3.w};
            #pragma unroll
            for (int j = 0; j < 16; j++) Bs[j * 256 + tid] = v[j];
        }
        __syncthreads();

        if (ko < 15) {
            const int kb = (ko + 1) * 16;
            va  = *(const float4*)(emb + (size_t)idx[arow] * E_ + kb + aq * 4);
            vb0 = *(const float4*)(Wm + (size_t)tid * E_ + kb + 0);
            vb1 = *(const float4*)(Wm + (size_t)tid * E_ + kb + 4);
            vb2 = *(const float4*)(Wm + (size_t)tid * E_ + kb + 8);
            vb3 = *(const float4*)(Wm + (size_t)tid * E_ + kb + 12);
        }

        #pragma unroll
        for (int k = 0; k < 16; k++) {
            u64t ap[4];
            #pragma unroll
            for (int i = 0; i < 4; i++)
                ap[i] = *(const u64t*)&As2[k * 64 + ty * 4 + i];
            #pragma unroll
            for (int q = 0; q < 4; q++) {
                const ulonglong2 bq = *(const ulonglong2*)&Bs[k * 256 + q * 64 + tx * 4];
                #pragma unroll
                for (int i = 0; i < 4; i++) {
                    acc[i][2 * q + 0] = ffma2(bq.x, ap[i], acc[i][2 * q + 0]);
                    acc[i][2 * q + 1] = ffma2(bq.y, ap[i], acc[i][2 * q + 1]);
                }
            }
        }
    }

    #pragma unroll
    for (int i = 0; i < 4; i++) {
        const int rg = r0 + ty * 4 + i;
        #pragma unroll
        for (int q = 0; q < 4; q++) {
            float4 o;
            o.x = f2lo(acc[i][2 * q + 0]); o.y = f2hi(acc[i][2 * q + 0]);
            o.z = f2lo(acc[i][2 * q + 1]); o.w = f2hi(acc[i][2 * q + 1]);
            __stcs((float4*)(g_xw + (size_t)rg * U_ + q * 64 + tx * 4), o);
        }
    }
}

// ---------------------------------------------------------------------------
// Phase 2: recurrence (R4 cluster structure, retiled + mbar sync).
// Cluster of 2 CTAs per batch pair. CTA rank holds U rows [rank*128,+128) x
// ALL 256 cols in regs: thread (uu=tid>>3, ju=tid&7) owns rows uhalf+uu*4+a
// (4 rows), cols ju*32..+31 -> Ur[4][16] = 64 u64 = 128 regs.
// Per step: 16 LDS.128 of h (both batches), 128 FFMA2 -> v[8] partials
// (2 batches x 4 rows), 7-shfl reduce over the 8 ju lanes -> lane ju holds
// ONE (batch=ju>>2, row=ju&3) dot -> 1 tanh, 1 local STS + 1 st.async to
// peer (tx-counted, 1024B/step), 1 bar. No barrier.cluster in the loop.
// ---------------------------------------------------------------------------
__global__ void __cluster_dims__(2, 1, 1) __launch_bounds__(256, 1)
rnn_kernel(const float* __restrict__ Um,
           const float* __restrict__ W1, const float* __restrict__ b1v,
           const float* __restrict__ W2, const float* __restrict__ b2v,
           float* __restrict__ outp)
{
    __shared__ __align__(16) float hbuf[2][2][256];     // [buf][batch][u], full h mirror
    __shared__ __align__(8)  unsigned long long mbar[2];
    __shared__ __align__(16) float hfin[2][256];
    __shared__ float hid[2][32];

    const int tid = threadIdx.x;
    unsigned rank;
    asm("mov.u32 %0, %%cluster_ctarank;" : "=r"(rank));
    const unsigned peer = rank ^ 1u;
    const int b0 = (blockIdx.x >> 1) * 2;
    const int uhalf = (int)rank * 128;
    const int uu = tid >> 3;            // 0..31 -> 4 rows each
    const int ju = tid & 7;             // 0..7  -> 32-col chunk
    const int jb = ju * 32;

    // U rows uhalf+uu*4+a, cols jb..jb+31 -> Ur[4][16] (64 u64)
    u64t Ur[4][16];
    #pragma unroll
    for (int a = 0; a < 4; a++) {
        const u64t* p = (const u64t*)(Um + (size_t)(uhalf + uu * 4 + a) * U_ + jb);
        #pragma unroll
        for (int q = 0; q < 16; q++) Ur[a][q] = p[q];
    }

    for (int k = tid; k < 1024; k += 256) ((float*)hbuf)[k] = 0.0f;

    const unsigned lh = (unsigned)__cvta_generic_to_shared(hbuf);
    const unsigned lb = (unsigned)__cvta_generic_to_shared(mbar);
    const unsigned lf = (unsigned)__cvta_generic_to_shared(hfin);
    unsigned rh, rb_, r0f;
    asm("mapa.shared::cluster.u32 %0, %1, %2;" : "=r"(rh)  : "r"(lh), "r"(peer));
    asm("mapa.shared::cluster.u32 %0, %1, %2;" : "=r"(rb_) : "r"(lb), "r"(peer));
    asm("mapa.shared::cluster.u32 %0, %1, %2;" : "=r"(r0f) : "r"(lf), "r"(0u));

    if (tid == 0) {
        mbar_init(lb + 0, 1);
        mbar_init(lb + 8, 1);
        mbar_expect(lb + 0, 1024);   // arm for arrivals at t=1 (writes to buf 0)
        mbar_expect(lb + 8, 1024);   // arm for arrivals at t=0 (writes to buf 1)
    }
    __syncthreads();
    cluster_sync_();                 // peer init + hbuf zeros visible

    // lane role: batch beta = ju>>2, row a = ju&3
    const int beta = ju >> 2;
    const int u_fin = uhalf + uu * 4 + (ju & 3);
    unsigned ph[2] = {0u, 0u};
    const unsigned FM = 0xffffffffu;

    float cxw = __ldcs(g_xw + (size_t)(b0 + beta) * U_ + u_fin);
    float hval = 0.0f;

    for (int t = 0; t < T_; t++) {
        const int rb = t & 1;
        const int wb = rb ^ 1;

        if (t > 0) {
            mbar_wait(lb + rb * 8, ph[rb]);
            ph[rb] ^= 1u;
            if (tid == 0) mbar_expect(lb + rb * 8, 1024);   // re-arm for step t+2
        }

        // prefetch next step's xw
        const int tn = (t + 1 < T_) ? t + 1 : t;
        const float nxw = __ldcs(g_xw + (size_t)tn * (B_ * U_) + (size_t)(b0 + beta) * U_ + u_fin);

        // partial dots: 2 batches x 4 rows over my 32-col chunk
        float v[8];
        #pragma unroll
        for (int B2 = 0; B2 < 2; B2++) {
            u64t hv[16];
            const ulonglong2* hp = (const ulonglong2*)&hbuf[rb][B2][jb];
            #pragma unroll
            for (int k = 0; k < 8; k++) {
                const ulonglong2 h2 = hp[k];
                hv[2 * k + 0] = h2.x;
                hv[2 * k + 1] = h2.y;
            }
            #pragma unroll
            for (int a = 0; a < 4; a++) {
                u64t ac0 = 0ull, ac1 = 0ull;
                #pragma unroll
                for (int q = 0; q < 8; q++) {
                    ac0 = ffma2(Ur[a][2 * q + 0], hv[2 * q + 0], ac0);
                    ac1 = ffma2(Ur[a][2 * q + 1], hv[2 * q + 1], ac1);
                }
                const u64t s = addx2(ac0, ac1);
                v[B2 * 4 + a] = f2lo(s) + f2hi(s);
            }
        }

        // reduce-scatter 8 values over the 8 ju lanes (xor 4, 2, 1)
        float w[4];
        {
            const bool hi = (ju & 4) != 0;
            #pragma unroll
            for (int a = 0; a < 4; a++) {
                const float keep = hi ? v[a + 4] : v[a];
                const float send = hi ? v[a] : v[a + 4];
                w[a] = keep + __shfl_xor_sync(FM, send, 4);
            }
        }
        float x[2];
        {
            const bool hi = (ju & 2) != 0;
            #pragma unroll
            for (int a = 0; a < 2; a++) {
                const float keep = hi ? x[0] * 0.0f + w[a + 2] : w[a];   // select
                const float send = hi ? w[a] : w[a + 2];
                x[a] = keep + __shfl_xor_sync(FM, send, 2);
            }
        }
        float d;
        {
            const bool hi = (ju & 1) != 0;
            const float keep = hi ? x[1] : x[0];
            const float send = hi ? x[0] : x[1];
            d = keep + __shfl_xor_sync(FM, send, 1);
        }

        hval = tanh_fast(d + cxw);
        const int off = wb * 512 + beta * 256 + u_fin;
        hbuf[wb][beta][u_fin] = hval;
        st_async_f32(rh + (unsigned)off * 4, hval, rb_ + (unsigned)wb * 8);

        __syncthreads();     // local-half visibility for next step
        cxw = nxw;
    }

    // each lane holds final h for (beta, u_fin); gather on rank0 and run head
    st_cluster_f32(r0f + (unsigned)(beta * 256 + u_fin) * 4, hval);
    cluster_sync_();

    if (rank == 0) {
        if (tid < 32) {
            for (int bi = 0; bi < 2; bi++) {
                float acc = b1v[tid];
                const float* hr = hfin[bi];
                #pragma unroll 8
                for (int j = 0; j < 256; j++)
                    acc = fmaf(hr[j], __ldg(W1 + j * 32 + tid), acc);
                hid[bi][tid] = fmaxf(acc, 0.0f);
            }
        }
        __syncthreads();
        if (tid < 2) {
            float l0 = b2v[0], l1 = b2v[1];
            #pragma unroll
            for (int k = 0; k < 32; k++) {
                const float hv2 = hid[tid][k];
                l0 = fmaf(hv2, __ldg(W2 + k * 2 + 0), l0);
                l1 = fmaf(hv2, __ldg(W2 + k * 2 + 1), l1);
            }
            const float m = fmaxf(l0, l1);
            const float e0 = expf(l0 - m);
            const float e1 = expf(l1 - m);
            const float inv = 1.0f / (e0 + e1);
            outp[(b0 + tid) * 2 + 0] = e0 * inv;
            outp[(b0 + tid) * 2 + 1] = e1 * inv;
        }
    }
    cluster_sync_();   // no CTA exits while peer traffic may be in flight
}

// ---------------------------------------------------------------------------
extern "C" void kernel_launch(void* const* d_in, const int* in_sizes, int n_in,
                              void* d_out, int out_size)
{
    const int*   sent = (const int*)d_in[0];
    const float* emb  = (const float*)d_in[1];
    const float* Wm   = (const float*)d_in[2];
    const float* Um   = (const float*)d_in[3];
    const float* W1   = (const float*)d_in[4];
    const float* b1v  = (const float*)d_in[5];
    const float* W2   = (const float*)d_in[6];
    const float* b2v  = (const float*)d_in[7];
    float* outp = (float*)d_out;
    (void)in_sizes; (void)n_in; (void)out_size;

    xw_kernel<<<1024, 256>>>(sent, emb, Wm);
    rnn_kernel<<<128, 256>>>(Um, W1, b1v, W2, b2v, outp);
}

// round 12
// speedup vs baseline: 1.1791x; 1.1791x over previous
#include <cuda_runtime.h>
#include <cuda_bf16.h>

#define B_ 128
#define T_ 512
#define E_ 256
#define U_ 256

#define HSTRIDE 20          // padded floats per 16-float h chunk
#define HBATCH  (16 * HSTRIDE)          // 320 floats per (buf,batch)
#define EXPECT_TX 1024u     // 256 st.async x 4B per CTA per step

typedef unsigned long long u64t;

// 64MB scratch: xw[t][b][u]
__device__ __align__(16) float g_xw[T_ * B_ * U_];

__device__ __forceinline__ u64t ffma2(u64t a, u64t b, u64t c) {
    u64t d;
    asm("fma.rn.f32x2 %0, %1, %2, %3;" : "=l"(d) : "l"(a), "l"(b), "l"(c));
    return d;
}
__device__ __forceinline__ u64t addx2(u64t a, u64t b) {
    u64t d;
    asm("add.rn.f32x2 %0, %1, %2;" : "=l"(d) : "l"(a), "l"(b));
    return d;
}
__device__ __forceinline__ float f2lo(u64t v) { return __uint_as_float((unsigned)(v & 0xffffffffull)); }
__device__ __forceinline__ float f2hi(u64t v) { return __uint_as_float((unsigned)(v >> 32)); }
__device__ __forceinline__ float tanh_fast(float x) {
    float ex = __expf(2.0f * x);
    return 1.0f - __fdividef(2.0f, ex + 1.0f);
}

// ---------------- mbarrier / cluster helpers ----------------
__device__ __forceinline__ void mbar_init(unsigned addr, unsigned cnt) {
    asm volatile("mbarrier.init.shared.b64 [%0], %1;" :: "r"(addr), "r"(cnt) : "memory");
}
__device__ __forceinline__ void mbar_expect(unsigned addr, unsigned bytes) {
    asm volatile("mbarrier.arrive.expect_tx.shared.b64 _, [%0], %1;"
                 :: "r"(addr), "r"(bytes) : "memory");
}
__device__ __forceinline__ void mbar_wait(unsigned addr, unsigned parity) {
    unsigned done;
    asm volatile(
        "{\n\t.reg .pred p;\n\t"
        "mbarrier.try_wait.parity.acquire.cta.shared::cta.b64 p, [%1], %2;\n\t"
        "selp.b32 %0, 1, 0, p;\n\t}"
        : "=r"(done) : "r"(addr), "r"(parity) : "memory");
    if (!done) {
        asm volatile(
            "{\n\t.reg .pred P1;\n\t"
            "W_%=:\n\t"
            "mbarrier.try_wait.parity.acquire.cta.shared::cta.b64 P1, [%0], %1, 0x989680;\n\t"
            "@P1 bra D_%=;\n\t"
            "bra W_%=;\n\t"
            "D_%=:\n\t}"
            :: "r"(addr), "r"(parity) : "memory");
    }
}
__device__ __forceinline__ void st_async_f32(unsigned raddr, float v, unsigned rbar) {
    asm volatile("st.async.shared::cluster.mbarrier::complete_tx::bytes.b32 [%0], %1, [%2];"
                 :: "r"(raddr), "r"(__float_as_uint(v)), "r"(rbar) : "memory");
}
__device__ __forceinline__ void st_cluster_f32(unsigned raddr, float v) {
    asm volatile("st.shared::cluster.f32 [%0], %1;" :: "r"(raddr), "f"(v) : "memory");
}
__device__ __forceinline__ void cluster_sync_() {
    asm volatile("barrier.cluster.arrive.aligned;" ::: "memory");
    asm volatile("barrier.cluster.wait.aligned;" ::: "memory");
}

// ---------------------------------------------------------------------------
// Phase 1: xw[t][b][u] = sum_e emb[sentence[b][t]][e] * W[u][e]  (unchanged)
// ---------------------------------------------------------------------------
__global__ void __launch_bounds__(256)
xw_kernel(const int* __restrict__ sent, const float* __restrict__ emb,
          const float* __restrict__ Wm)
{
    __shared__ __align__(16) float2 As2[16 * 64];
    __shared__ __align__(16) float  Bs[16 * 256];
    __shared__ int idx[64];

    const int tid = threadIdx.x;
    const int r0 = blockIdx.x * 64;
    const int t  = r0 >> 7;
    const int b0 = r0 & 127;

    if (tid < 64) idx[tid] = sent[(b0 + tid) * T_ + t];
    __syncthreads();

    const int tx = tid & 15;
    const int ty = tid >> 4;
    const int arow = tid >> 2;
    const int aq = tid & 3;

    u64t acc[4][8];
    #pragma unroll
    for (int i = 0; i < 4; i++)
        #pragma unroll
        for (int p = 0; p < 8; p++) acc[i][p] = 0ull;

    float4 va = *(const float4*)(emb + (size_t)idx[arow] * E_ + aq * 4);
    float4 vb0 = *(const float4*)(Wm + (size_t)tid * E_ + 0);
    float4 vb1 = *(const float4*)(Wm + (size_t)tid * E_ + 4);
    float4 vb2 = *(const float4*)(Wm + (size_t)tid * E_ + 8);
    float4 vb3 = *(const float4*)(Wm + (size_t)tid * E_ + 12);

    for (int ko = 0; ko < 16; ko++) {
        if (ko > 0) __syncthreads();

        As2[(aq * 4 + 0) * 64 + arow] = make_float2(va.x, va.x);
        As2[(aq * 4 + 1) * 64 + arow] = make_float2(va.y, va.y);
        As2[(aq * 4 + 2) * 64 + arow] = make_float2(va.z, va.z);
        As2[(aq * 4 + 3) * 64 + arow] = make_float2(va.w, va.w);
        {
            const float v[16] = {vb0.x, vb0.y, vb0.z, vb0.w, vb1.x, vb1.y, vb1.z, vb1.w,
                                 vb2.x, vb2.y, vb2.z, vb2.w, vb3.x, vb3.y, vb3.z, vb3.w};
            #pragma unroll
            for (int j = 0; j < 16; j++) Bs[j * 256 + tid] = v[j];
        }
        __syncthreads();

        if (ko < 15) {
            const int kb = (ko + 1) * 16;
            va  = *(const float4*)(emb + (size_t)idx[arow] * E_ + kb + aq * 4);
            vb0 = *(const float4*)(Wm + (size_t)tid * E_ + kb + 0);
            vb1 = *(const float4*)(Wm + (size_t)tid * E_ + kb + 4);
            vb2 = *(const float4*)(Wm + (size_t)tid * E_ + kb + 8);
            vb3 = *(const float4*)(Wm + (size_t)tid * E_ + kb + 12);
        }

        #pragma unroll
        for (int k = 0; k < 16; k++) {
            u64t ap[4];
            #pragma unroll
            for (int i = 0; i < 4; i++)
                ap[i] = *(const u64t*)&As2[k * 64 + ty * 4 + i];
            #pragma unroll
            for (int q = 0; q < 4; q++) {
                const ulonglong2 bq = *(const ulonglong2*)&Bs[k * 256 + q * 64 + tx * 4];
                #pragma unroll
                for (int i = 0; i < 4; i++) {
                    acc[i][2 * q + 0] = ffma2(bq.x, ap[i], acc[i][2 * q + 0]);
                    acc[i][2 * q + 1] = ffma2(bq.y, ap[i], acc[i][2 * q + 1]);
                }
            }
        }
    }

    #pragma unroll
    for (int i = 0; i < 4; i++) {
        const int rg = r0 + ty * 4 + i;
        #pragma unroll
        for (int q = 0; q < 4; q++) {
            float4 o;
            o.x = f2lo(acc[i][2 * q + 0]); o.y = f2hi(acc[i][2 * q + 0]);
            o.z = f2lo(acc[i][2 * q + 1]); o.w = f2hi(acc[i][2 * q + 1]);
            __stcs((float4*)(g_xw + (size_t)rg * U_ + q * 64 + tx * 4), o);
        }
    }
}

// ---------------------------------------------------------------------------
// Phase 2: recurrence — R4 structure & protocol, 512 threads (4 warps/SMSP).
// Cluster of 2 CTAs per batch pair; CTA rank holds U rows [rank*128,+128).
// Thread (uu=tid>>4, ju=tid&15): rows uhalf+uu*4+{0..3}, cols ju*16..+15
// (Ur[4][8] = 64 regs). Per step: 8 LDS.128 (padded chunks, ~2 phases),
// 64 FFMA2, 15-shfl reduce-scatter within 16-lane halves; lanes ju<8
// finalize ONE (batch=(ju>>2)&1, row=ju&3): tanh + local STS + st.async.
// Sync protocol identical to the proven R4 kernel.
// ---------------------------------------------------------------------------
__global__ void __cluster_dims__(2, 1, 1) __launch_bounds__(512, 1)
rnn_kernel(const float* __restrict__ Um,
           const float* __restrict__ W1, const float* __restrict__ b1v,
           const float* __restrict__ W2, const float* __restrict__ b2v,
           float* __restrict__ outp)
{
    __shared__ __align__(16) float hbuf[2][2][HBATCH];  // [buf][batch][chunk*20+slot]
    __shared__ __align__(8)  unsigned long long mbar[2];
    __shared__ __align__(16) float hfin[2][256];
    __shared__ float hid[2][32];

    const int tid = threadIdx.x;
    unsigned rank;
    asm("mov.u32 %0, %%cluster_ctarank;" : "=r"(rank));
    const unsigned peer = rank ^ 1u;
    const int b0 = (blockIdx.x >> 1) * 2;
    const int uhalf = (int)rank * 128;
    const int uu = tid >> 4;            // 0..31, 4 rows each
    const int ju = tid & 15;            // 16-col chunk
    const int jb = ju * 16;

    // U rows uhalf+uu*4+a, cols jb..jb+15 -> Ur[4][8] (32 u64 = 64 regs)
    u64t Ur[4][8];
    #pragma unroll
    for (int a = 0; a < 4; a++) {
        const u64t* p = (const u64t*)(Um + (size_t)(uhalf + uu * 4 + a) * U_ + jb);
        #pragma unroll
        for (int q = 0; q < 8; q++) Ur[a][q] = p[q];
    }

    for (int k = tid; k < 2 * 2 * HBATCH; k += 512) ((float*)hbuf)[k] = 0.0f;

    const unsigned lh = (unsigned)__cvta_generic_to_shared(hbuf);
    const unsigned lb = (unsigned)__cvta_generic_to_shared(mbar);
    const unsigned lf = (unsigned)__cvta_generic_to_shared(hfin);
    unsigned rh, rb_, r0f;
    asm("mapa.shared::cluster.u32 %0, %1, %2;" : "=r"(rh)  : "r"(lh), "r"(peer));
    asm("mapa.shared::cluster.u32 %0, %1, %2;" : "=r"(rb_) : "r"(lb), "r"(peer));
    asm("mapa.shared::cluster.u32 %0, %1, %2;" : "=r"(r0f) : "r"(lf), "r"(0u));

    if (tid == 0) {
        mbar_init(lb + 0, 1);
        mbar_init(lb + 8, 1);
        mbar_expect(lb + 8, EXPECT_TX);  // pre-arm buf1 (R4 protocol)
    }
    __syncthreads();
    cluster_sync_();                     // peer init + zeros visible

    // finalize role (lanes ju<8 store; ju>=8 duplicate, no store)
    const int batch = (ju >> 2) & 1;
    const int u_fin = uhalf + uu * 4 + (ju & 3);
    const bool storer = (ju < 8);
    const int cf = u_fin >> 4, sf = u_fin & 15;

    unsigned ph[2] = {0u, 0u};
    const unsigned FM = 0xffffffffu;

    float cxw = __ldcs(g_xw + (size_t)(b0 + batch) * U_ + u_fin);
    float hval = 0.0f;

    for (int t = 0; t < T_; t++) {
        const int rbuf = t & 1;
        const int wbuf = rbuf ^ 1;

        if (t > 0) {
            mbar_wait(lb + rbuf * 8, ph[rbuf]);
            ph[rbuf] ^= 1u;
        }
        if (tid == 0) mbar_expect(lb + rbuf * 8, EXPECT_TX);  // re-arm (R4 order)

        // prefetch next step's xw
        const int tn = (t + 1 < T_) ? t + 1 : t;
        const float nxw = __ldcs(g_xw + (size_t)tn * (B_ * U_) +
                                 (size_t)(b0 + batch) * U_ + u_fin);

        // partial dots: 2 batches x 4 rows over my 16-col chunk
        float v[8];
        #pragma unroll
        for (int B2 = 0; B2 < 2; B2++) {
            u64t hv[8];
            {
                const ulonglong2* hp =
                    (const ulonglong2*)&hbuf[rbuf][B2][ju * HSTRIDE];
                #pragma unroll
                for (int k = 0; k < 4; k++) {
                    const ulonglong2 h2 = hp[k];
                    hv[2 * k + 0] = h2.x;
                    hv[2 * k + 1] = h2.y;
                }
            }
            #pragma unroll
            for (int a = 0; a < 4; a++) {
                u64t ac0 = 0ull, ac1 = 0ull;
                #pragma unroll
                for (int q = 0; q < 4; q++) {
                    ac0 = ffma2(Ur[a][2 * q + 0], hv[2 * q + 0], ac0);
                    ac1 = ffma2(Ur[a][2 * q + 1], hv[2 * q + 1], ac1);
                }
                const u64t s = addx2(ac0, ac1);
                v[B2 * 4 + a] = f2lo(s) + f2hi(s);
            }
        }

        // reduce-scatter over 16-lane halves: lane ju ends with value (ju&7)
        // step 1 (mask 8): plain allreduce of the 8 values across halves
        #pragma unroll
        for (int a = 0; a < 8; a++) v[a] += __shfl_xor_sync(FM, v[a], 8);
        float w[4];
        {
            const bool hi = (ju & 4) != 0;
            #pragma unroll
            for (int a = 0; a < 4; a++) {
                const float keep = hi ? v[a + 4] : v[a];
                const float send = hi ? v[a] : v[a + 4];
                w[a] = keep + __shfl_xor_sync(FM, send, 4);
            }
        }
        float x[2];
        {
            const bool hi = (ju & 2) != 0;
            #pragma unroll
            for (int a = 0; a < 2; a++) {
                const float keep = hi ? w[a + 2] : w[a];
                const float send = hi ? w[a] : w[a + 2];
                x[a] = keep + __shfl_xor_sync(FM, send, 2);
            }
        }
        float d;
        {
            const bool hi = (ju & 1) != 0;
            const float keep = hi ? x[1] : x[0];
            const float send = hi ? x[0] : x[1];
            d = keep + __shfl_xor_sync(FM, send, 1);
        }

        hval = tanh_fast(d + cxw);
        if (storer) {
            const unsigned off = (unsigned)((wbuf * 2 + batch) * HBATCH +
                                            cf * HSTRIDE + sf);
            hbuf[wbuf][batch][cf * HSTRIDE + sf] = hval;
            st_async_f32(rh + off * 4u, hval, rb_ + (unsigned)wbuf * 8u);
        }

        __syncthreads();
        cxw = nxw;
    }

    // lanes ju<8 hold final h for (batch, u_fin); gather on rank0, run head
    if (storer) st_cluster_f32(r0f + (unsigned)(batch * 256 + u_fin) * 4u, hval);
    cluster_sync_();

    if (rank == 0) {
        if (tid < 32) {
            for (int bi = 0; bi < 2; bi++) {
                float acc = b1v[tid];
                const float* hr = hfin[bi];
                #pragma unroll 8
                for (int j = 0; j < 256; j++)
                    acc = fmaf(hr[j], __ldg(W1 + j * 32 + tid), acc);
                hid[bi][tid] = fmaxf(acc, 0.0f);
            }
        }
        __syncthreads();
        if (tid < 2) {
            float l0 = b2v[0], l1 = b2v[1];
            #pragma unroll
            for (int k = 0; k < 32; k++) {
                const float hv2 = hid[tid][k];
                l0 = fmaf(hv2, __ldg(W2 + k * 2 + 0), l0);
                l1 = fmaf(hv2, __ldg(W2 + k * 2 + 1), l1);
            }
            const float m = fmaxf(l0, l1);
            const float e0 = expf(l0 - m);
            const float e1 = expf(l1 - m);
            const float inv = 1.0f / (e0 + e1);
            outp[(b0 + tid) * 2 + 0] = e0 * inv;
            outp[(b0 + tid) * 2 + 1] = e1 * inv;
        }
    }
    cluster_sync_();   // no CTA exits while peer traffic may be in flight
}

// ---------------------------------------------------------------------------
extern "C" void kernel_launch(void* const* d_in, const int* in_sizes, int n_in,
                              void* d_out, int out_size)
{
    const int*   sent = (const int*)d_in[0];
    const float* emb  = (const float*)d_in[1];
    const float* Wm   = (const float*)d_in[2];
    const float* Um   = (const float*)d_in[3];
    const float* W1   = (const float*)d_in[4];
    const float* b1v  = (const float*)d_in[5];
    const float* W2   = (const float*)d_in[6];
    const float* b2v  = (const float*)d_in[7];
    float* outp = (float*)d_out;
    (void)in_sizes; (void)n_in; (void)out_size;

    xw_kernel<<<1024, 256>>>(sent, emb, Wm);
    rnn_kernel<<<128, 512>>>(Um, W1, b1v, W2, b2v, outp);
}

// round 13
// speedup vs baseline: 1.7263x; 1.4641x over previous
#include <cuda_runtime.h>
#include <cuda_bf16.h>

#define B_ 128
#define T_ 512
#define E_ 256
#define U_ 256

#define CH 18                 // padded floats per 16-float h chunk (72B, 8B-aligned)
#define HB (16 * CH)          // 288 floats per (buf,batch)

typedef unsigned long long u64t;

// 64MB scratch: xw[t][b][u]
__device__ __align__(16) float g_xw[T_ * B_ * U_];

__device__ __forceinline__ u64t ffma2(u64t a, u64t b, u64t c) {
    u64t d;
    asm("fma.rn.f32x2 %0, %1, %2, %3;" : "=l"(d) : "l"(a), "l"(b), "l"(c));
    return d;
}
__device__ __forceinline__ float f2lo(u64t v) { return __uint_as_float((unsigned)(v & 0xffffffffull)); }
__device__ __forceinline__ float f2hi(u64t v) { return __uint_as_float((unsigned)(v >> 32)); }
__device__ __forceinline__ float tanh_fast(float x) {
    float ex = __expf(2.0f * x);
    return 1.0f - __fdividef(2.0f, ex + 1.0f);
}

// ---------------- mbarrier / cluster helpers ----------------
__device__ __forceinline__ void mbar_init(unsigned addr, unsigned cnt) {
    asm volatile("mbarrier.init.shared.b64 [%0], %1;" :: "r"(addr), "r"(cnt) : "memory");
}
__device__ __forceinline__ void mbar_expect(unsigned addr, unsigned bytes) {
    asm volatile("mbarrier.arrive.expect_tx.shared.b64 _, [%0], %1;"
                 :: "r"(addr), "r"(bytes) : "memory");
}
__device__ __forceinline__ void mbar_wait(unsigned addr, unsigned parity) {
    unsigned done;
    asm volatile(
        "{\n\t.reg .pred p;\n\t"
        "mbarrier.try_wait.parity.acquire.cta.shared::cta.b64 p, [%1], %2;\n\t"
        "selp.b32 %0, 1, 0, p;\n\t}"
        : "=r"(done) : "r"(addr), "r"(parity) : "memory");
    if (!done) {
        asm volatile(
            "{\n\t.reg .pred P1;\n\t"
            "W_%=:\n\t"
            "mbarrier.try_wait.parity.acquire.cta.shared::cta.b64 P1, [%0], %1, 0x989680;\n\t"
            "@P1 bra D_%=;\n\t"
            "bra W_%=;\n\t"
            "D_%=:\n\t}"
            :: "r"(addr), "r"(parity) : "memory");
    }
}
__device__ __forceinline__ void st_async_f32(unsigned raddr, float v, unsigned rbar) {
    asm volatile("st.async.shared::cluster.mbarrier::complete_tx::bytes.b32 [%0], %1, [%2];"
                 :: "r"(raddr), "r"(__float_as_uint(v)), "r"(rbar) : "memory");
}
__device__ __forceinline__ void st_cluster_f32(unsigned raddr, float v) {
    asm volatile("st.shared::cluster.f32 [%0], %1;" :: "r"(raddr), "f"(v) : "memory");
}
__device__ __forceinline__ void cluster_sync_() {
    asm volatile("barrier.cluster.arrive.aligned;" ::: "memory");
    asm volatile("barrier.cluster.wait.aligned;" ::: "memory");
}

// ---------------------------------------------------------------------------
// Phase 1: xw[t][b][u] = sum_e emb[sentence[b][t]][e] * W[u][e]  (unchanged)
// ---------------------------------------------------------------------------
__global__ void __launch_bounds__(256)
xw_kernel(const int* __restrict__ sent, const float* __restrict__ emb,
          const float* __restrict__ Wm)
{
    __shared__ __align__(16) float2 As2[16 * 64];
    __shared__ __align__(16) float  Bs[16 * 256];
    __shared__ int idx[64];

    const int tid = threadIdx.x;
    const int r0 = blockIdx.x * 64;
    const int t  = r0 >> 7;
    const int b0 = r0 & 127;

    if (tid < 64) idx[tid] = sent[(b0 + tid) * T_ + t];
    __syncthreads();

    const int tx = tid & 15;
    const int ty = tid >> 4;
    const int arow = tid >> 2;
    const int aq = tid & 3;

    u64t acc[4][8];
    #pragma unroll
    for (int i = 0; i < 4; i++)
        #pragma unroll
        for (int p = 0; p < 8; p++) acc[i][p] = 0ull;

    float4 va = *(const float4*)(emb + (size_t)idx[arow] * E_ + aq * 4);
    float4 vb0 = *(const float4*)(Wm + (size_t)tid * E_ + 0);
    float4 vb1 = *(const float4*)(Wm + (size_t)tid * E_ + 4);
    float4 vb2 = *(const float4*)(Wm + (size_t)tid * E_ + 8);
    float4 vb3 = *(const float4*)(Wm + (size_t)tid * E_ + 12);

    for (int ko = 0; ko < 16; ko++) {
        if (ko > 0) __syncthreads();

        As2[(aq * 4 + 0) * 64 + arow] = make_float2(va.x, va.x);
        As2[(aq * 4 + 1) * 64 + arow] = make_float2(va.y, va.y);
        As2[(aq * 4 + 2) * 64 + arow] = make_float2(va.z, va.z);
        As2[(aq * 4 + 3) * 64 + arow] = make_float2(va.w, va.w);
        {
            const float v[16] = {vb0.x, vb0.y, vb0.z, vb0.w, vb1.x, vb1.y, vb1.z, vb1.w,
                                 vb2.x, vb2.y, vb2.z, vb2.w, vb3.x, vb3.y, vb3.z, vb3.w};
            #pragma unroll
            for (int j = 0; j < 16; j++) Bs[j * 256 + tid] = v[j];
        }
        __syncthreads();

        if (ko < 15) {
            const int kb = (ko + 1) * 16;
            va  = *(const float4*)(emb + (size_t)idx[arow] * E_ + kb + aq * 4);
            vb0 = *(const float4*)(Wm + (size_t)tid * E_ + kb + 0);
            vb1 = *(const float4*)(Wm + (size_t)tid * E_ + kb + 4);
            vb2 = *(const float4*)(Wm + (size_t)tid * E_ + kb + 8);
            vb3 = *(const float4*)(Wm + (size_t)tid * E_ + kb + 12);
        }

        #pragma unroll
        for (int k = 0; k < 16; k++) {
            u64t ap[4];
            #pragma unroll
            for (int i = 0; i < 4; i++)
                ap[i] = *(const u64t*)&As2[k * 64 + ty * 4 + i];
            #pragma unroll
            for (int q = 0; q < 4; q++) {
                const ulonglong2 bq = *(const ulonglong2*)&Bs[k * 256 + q * 64 + tx * 4];
                #pragma unroll
                for (int i = 0; i < 4; i++) {
                    acc[i][2 * q + 0] = ffma2(bq.x, ap[i], acc[i][2 * q + 0]);
                    acc[i][2 * q + 1] = ffma2(bq.y, ap[i], acc[i][2 * q + 1]);
                }
            }
        }
    }

    #pragma unroll
    for (int i = 0; i < 4; i++) {
        const int rg = r0 + ty * 4 + i;
        #pragma unroll
        for (int q = 0; q < 4; q++) {
            float4 o;
            o.x = f2lo(acc[i][2 * q + 0]); o.y = f2hi(acc[i][2 * q + 0]);
            o.z = f2lo(acc[i][2 * q + 1]); o.w = f2hi(acc[i][2 * q + 1]);
            __stcs((float4*)(g_xw + (size_t)rg * U_ + q * 64 + tx * 4), o);
        }
    }
}

// ---------------------------------------------------------------------------
// Phase 2: recurrence — R4 structure (256 thr, Ur[8][8], per-value st.async)
// with (a) batch-split mbarriers so each DSMEM flight hides behind the other
// batch's compute, (b) padded h layout (16->18 floats/chunk) for
// conflict-free LDS.64 h reads.
// reduce16: lane ju ends with dot for row a = ju>>1 (lane pairs duplicate).
// ---------------------------------------------------------------------------
__device__ __forceinline__ float reduce16(const float v[8], int ju) {
    const unsigned FM = 0xffffffffu;
    float w[4];
    const bool t3 = (ju & 8) != 0;
    #pragma unroll
    for (int a = 0; a < 4; a++) {
        const float keep = t3 ? v[a + 4] : v[a];
        const float send = t3 ? v[a] : v[a + 4];
        w[a] = keep + __shfl_xor_sync(FM, send, 8);
    }
    float x[2];
    const bool t2 = (ju & 4) != 0;
    #pragma unroll
    for (int a = 0; a < 2; a++) {
        const float keep = t2 ? w[a + 2] : w[a];
        const float send = t2 ? w[a] : w[a + 2];
        x[a] = keep + __shfl_xor_sync(FM, send, 4);
    }
    const bool t1 = (ju & 2) != 0;
    const float keep = t1 ? x[1] : x[0];
    const float send = t1 ? x[0] : x[1];
    float y = keep + __shfl_xor_sync(FM, send, 2);
    y += __shfl_xor_sync(FM, y, 1);
    return y;
}

__global__ void __cluster_dims__(2, 1, 1) __launch_bounds__(256, 1)
rnn_kernel(const float* __restrict__ Um,
           const float* __restrict__ W1, const float* __restrict__ b1v,
           const float* __restrict__ W2, const float* __restrict__ b2v,
           float* __restrict__ outp)
{
    __shared__ __align__(16) float hbuf[2][2][HB];      // [buf][batch][chunk*18+slot]
    __shared__ __align__(8)  unsigned long long mbar[4]; // [batch*2+buf]
    __shared__ __align__(16) float hfin[2][256];
    __shared__ float hid[2][32];

    const int tid = threadIdx.x;
    unsigned rank;
    asm("mov.u32 %0, %%cluster_ctarank;" : "=r"(rank));
    const unsigned peer = rank ^ 1u;
    const int b0 = (blockIdx.x >> 1) * 2;
    const int b1i = b0 + 1;
    const int uhalf = (int)rank * 128;
    const int uu = tid >> 4;
    const int ju = tid & 15;

    // U chunk: rows u = uhalf + uu*8 + a, cols ju*16..+15
    u64t Ur[8][8];
    #pragma unroll
    for (int a = 0; a < 8; a++) {
        const u64t* p = (const u64t*)(Um + (size_t)(uhalf + uu * 8 + a) * U_ + ju * 16);
        #pragma unroll
        for (int q = 0; q < 8; q++) Ur[a][q] = p[q];
    }

    for (int k = tid; k < 2 * 2 * HB; k += 256) ((float*)hbuf)[k] = 0.0f;

    const unsigned lh = (unsigned)__cvta_generic_to_shared(hbuf);
    const unsigned lb = (unsigned)__cvta_generic_to_shared(mbar);
    const unsigned lf = (unsigned)__cvta_generic_to_shared(hfin);
    unsigned rh, rb_, r0f;
    asm("mapa.shared::cluster.u32 %0, %1, %2;" : "=r"(rh)  : "r"(lh), "r"(peer));
    asm("mapa.shared::cluster.u32 %0, %1, %2;" : "=r"(rb_) : "r"(lb), "r"(peer));
    asm("mapa.shared::cluster.u32 %0, %1, %2;" : "=r"(r0f) : "r"(lf), "r"(0u));

    if (tid == 0) {
        mbar_init(lb + 0,  1);   // [b0][buf0]
        mbar_init(lb + 8,  1);   // [b0][buf1]
        mbar_init(lb + 16, 1);   // [b1][buf0]
        mbar_init(lb + 24, 1);   // [b1][buf1]
        mbar_expect(lb + 8,  1024);   // arm buf1 for t=0 arrivals (batch0)
        mbar_expect(lb + 24, 1024);   // arm buf1 for t=0 arrivals (batch1)
    }
    __syncthreads();
    cluster_sync_();                 // peer init + hbuf zeros visible

    const int u_g = uhalf + uu * 8 + (ju >> 1);
    const int cf = u_g >> 4, sf = u_g & 15;          // padded write offset parts
    unsigned ph0[2] = {0u, 0u}, ph1[2] = {0u, 0u};

    float cxw0 = __ldcs(g_xw + (size_t)b0  * U_ + u_g);
    float cxw1 = __ldcs(g_xw + (size_t)b1i * U_ + u_g);
    float v0 = 0.0f, v1 = 0.0f;

    for (int t = 0; t < T_; t++) {
        const int rbuf = t & 1;
        const int wbuf = rbuf ^ 1;

        // ---- batch 0 ----
        if (t > 0) { mbar_wait(lb + (0 * 2 + rbuf) * 8, ph0[rbuf]); ph0[rbuf] ^= 1u; }
        if (tid == 0) mbar_expect(lb + (0 * 2 + rbuf) * 8, 1024);

        // prefetch next step's xw while in compute
        const int tn = (t + 1 < T_) ? t + 1 : t;
        const float nxw0 = __ldcs(g_xw + (size_t)tn * (B_ * U_) + b0  * U_ + u_g);
        const float nxw1 = __ldcs(g_xw + (size_t)tn * (B_ * U_) + b1i * U_ + u_g);

        {
            u64t h0[8];
            const u64t* hp0 = (const u64t*)&hbuf[rbuf][0][ju * CH];
            #pragma unroll
            for (int q = 0; q < 8; q++) h0[q] = hp0[q];

            float s0[8];
            #pragma unroll
            for (int a = 0; a < 8; a++) {
                u64t ac = 0ull;
                #pragma unroll
                for (int q = 0; q < 8; q++) ac = ffma2(Ur[a][q], h0[q], ac);
                s0[a] = f2lo(ac) + f2hi(ac);
            }
            const float d0 = reduce16(s0, ju);
            v0 = tanh_fast(d0 + cxw0);
            const unsigned off0 = (unsigned)((wbuf * 2 + 0) * HB + cf * CH + sf);
            hbuf[wbuf][0][cf * CH + sf] = v0;
            st_async_f32(rh + off0 * 4u, v0, rb_ + (unsigned)(0 * 2 + wbuf) * 8u);
        }

        // ---- batch 1 (b0's DSMEM flight hides behind this compute) ----
        if (t > 0) { mbar_wait(lb + (1 * 2 + rbuf) * 8, ph1[rbuf]); ph1[rbuf] ^= 1u; }
        if (tid == 0) mbar_expect(lb + (1 * 2 + rbuf) * 8, 1024);

        {
            u64t h1[8];
            const u64t* hp1 = (const u64t*)&hbuf[rbuf][1][ju * CH];
            #pragma unroll
            for (int q = 0; q < 8; q++) h1[q] = hp1[q];

            float s1[8];
            #pragma unroll
            for (int a = 0; a < 8; a++) {
                u64t ac = 0ull;
                #pragma unroll
                for (int q = 0; q < 8; q++) ac = ffma2(Ur[a][q], h1[q], ac);
                s1[a] = f2lo(ac) + f2hi(ac);
            }
            const float d1 = reduce16(s1, ju);
            v1 = tanh_fast(d1 + cxw1);
            const unsigned off1 = (unsigned)((wbuf * 2 + 1) * HB + cf * CH + sf);
            hbuf[wbuf][1][cf * CH + sf] = v1;
            st_async_f32(rh + off1 * 4u, v1, rb_ + (unsigned)(1 * 2 + wbuf) * 8u);
        }

        __syncthreads();   // local-half visibility for next step's reads
        cxw0 = nxw0; cxw1 = nxw1;
    }

    // owner lanes hold final h (duplicated pairs write same value) -> rank0
    st_cluster_f32(r0f + (unsigned)(0 * 256 + u_g) * 4u, v0);
    st_cluster_f32(r0f + (unsigned)(1 * 256 + u_g) * 4u, v1);
    cluster_sync_();

    if (rank == 0) {
        if (tid < 32) {
            for (int bi = 0; bi < 2; bi++) {
                float acc = b1v[tid];
                const float* hr = hfin[bi];
                #pragma unroll 8
                for (int j = 0; j < 256; j++)
                    acc = fmaf(hr[j], __ldg(W1 + j * 32 + tid), acc);
                hid[bi][tid] = fmaxf(acc, 0.0f);
            }
        }
        __syncthreads();
        if (tid < 2) {
            float l0 = b2v[0], l1 = b2v[1];
            #pragma unroll
            for (int k = 0; k < 32; k++) {
                const float hv = hid[tid][k];
                l0 = fmaf(hv, __ldg(W2 + k * 2 + 0), l0);
                l1 = fmaf(hv, __ldg(W2 + k * 2 + 1), l1);
            }
            const float m = fmaxf(l0, l1);
            const float e0 = expf(l0 - m);
            const float e1 = expf(l1 - m);
            const float inv = 1.0f / (e0 + e1);
            outp[(b0 + tid) * 2 + 0] = e0 * inv;
            outp[(b0 + tid) * 2 + 1] = e1 * inv;
        }
    }
    cluster_sync_();   // no CTA exits while peer traffic may be in flight
}

// ---------------------------------------------------------------------------
extern "C" void kernel_launch(void* const* d_in, const int* in_sizes, int n_in,
                              void* d_out, int out_size)
{
    const int*   sent = (const int*)d_in[0];
    const float* emb  = (const float*)d_in[1];
    const float* Wm   = (const float*)d_in[2];
    const float* Um   = (const float*)d_in[3];
    const float* W1   = (const float*)d_in[4];
    const float* b1v  = (const float*)d_in[5];
    const float* W2   = (const float*)d_in[6];
    const float* b2v  = (const float*)d_in[7];
    float* outp = (float*)d_out;
    (void)in_sizes; (void)n_in; (void)out_size;

    xw_kernel<<<1024, 256>>>(sent, emb, Wm);
    rnn_kernel<<<128, 256>>>(Um, W1, b1v, W2, b2v, outp);
}

// round 14
// speedup vs baseline: 2.2230x; 1.2877x over previous
#include <cuda_runtime.h>
#include <cuda_bf16.h>

#define B_ 128
#define T_ 512
#define E_ 256
#define U_ 256

#define CH 18                // padded floats per 16-float h chunk (72B)
#define HB (16 * CH)         // 288 floats per (buf,batch)

typedef unsigned long long u64t;

// 64MB scratch: xw[t][b][u]
__device__ __align__(16) float g_xw[T_ * B_ * U_];

__device__ __forceinline__ u64t ffma2(u64t a, u64t b, u64t c) {
    u64t d;
    asm("fma.rn.f32x2 %0, %1, %2, %3;" : "=l"(d) : "l"(a), "l"(b), "l"(c));
    return d;
}
__device__ __forceinline__ float f2lo(u64t v) { return __uint_as_float((unsigned)(v & 0xffffffffull)); }
__device__ __forceinline__ float f2hi(u64t v) { return __uint_as_float((unsigned)(v >> 32)); }
__device__ __forceinline__ float tanh_fast(float x) {
    float ex = __expf(2.0f * x);
    return 1.0f - __fdividef(2.0f, ex + 1.0f);
}

// ---------------- mbarrier / cluster helpers (R4 verbatim) ----------------
__device__ __forceinline__ void mbar_init(unsigned addr, unsigned cnt) {
    asm volatile("mbarrier.init.shared.b64 [%0], %1;" :: "r"(addr), "r"(cnt) : "memory");
}
__device__ __forceinline__ void mbar_expect(unsigned addr, unsigned bytes) {
    asm volatile("mbarrier.arrive.expect_tx.shared.b64 _, [%0], %1;"
                 :: "r"(addr), "r"(bytes) : "memory");
}
__device__ __forceinline__ void mbar_wait(unsigned addr, unsigned parity) {
    unsigned done;
    asm volatile(
        "{\n\t.reg .pred p;\n\t"
        "mbarrier.try_wait.parity.acquire.cta.shared::cta.b64 p, [%1], %2;\n\t"
        "selp.b32 %0, 1, 0, p;\n\t}"
        : "=r"(done) : "r"(addr), "r"(parity) : "memory");
    if (!done) {
        asm volatile(
            "{\n\t.reg .pred P1;\n\t"
            "W_%=:\n\t"
            "mbarrier.try_wait.parity.acquire.cta.shared::cta.b64 P1, [%0], %1, 0x989680;\n\t"
            "@P1 bra D_%=;\n\t"
            "bra W_%=;\n\t"
            "D_%=:\n\t}"
            :: "r"(addr), "r"(parity) : "memory");
    }
}
__device__ __forceinline__ void st_async_f32(unsigned raddr, float v, unsigned rbar) {
    asm volatile("st.async.shared::cluster.mbarrier::complete_tx::bytes.b32 [%0], %1, [%2];"
                 :: "r"(raddr), "r"(__float_as_uint(v)), "r"(rbar) : "memory");
}
__device__ __forceinline__ void cluster_sync_() {
    asm volatile("barrier.cluster.arrive.aligned;" ::: "memory");
    asm volatile("barrier.cluster.wait.aligned;" ::: "memory");
}

// ---------------------------------------------------------------------------
// Phase 1: xw[t][b][u] = sum_e emb[sentence[b][t]][e] * W[u][e]  (unchanged)
// ---------------------------------------------------------------------------
__global__ void __launch_bounds__(256)
xw_kernel(const int* __restrict__ sent, const float* __restrict__ emb,
          const float* __restrict__ Wm)
{
    __shared__ __align__(16) float2 As2[16 * 64];
    __shared__ __align__(16) float  Bs[16 * 256];
    __shared__ int idx[64];

    const int tid = threadIdx.x;
    const int r0 = blockIdx.x * 64;
    const int t  = r0 >> 7;
    const int b0 = r0 & 127;

    if (tid < 64) idx[tid] = sent[(b0 + tid) * T_ + t];
    __syncthreads();

    const int tx = tid & 15;
    const int ty = tid >> 4;
    const int arow = tid >> 2;
    const int aq = tid & 3;

    u64t acc[4][8];
    #pragma unroll
    for (int i = 0; i < 4; i++)
        #pragma unroll
        for (int p = 0; p < 8; p++) acc[i][p] = 0ull;

    float4 va = *(const float4*)(emb + (size_t)idx[arow] * E_ + aq * 4);
    float4 vb0 = *(const float4*)(Wm + (size_t)tid * E_ + 0);
    float4 vb1 = *(const float4*)(Wm + (size_t)tid * E_ + 4);
    float4 vb2 = *(const float4*)(Wm + (size_t)tid * E_ + 8);
    float4 vb3 = *(const float4*)(Wm + (size_t)tid * E_ + 12);

    for (int ko = 0; ko < 16; ko++) {
        if (ko > 0) __syncthreads();

        As2[(aq * 4 + 0) * 64 + arow] = make_float2(va.x, va.x);
        As2[(aq * 4 + 1) * 64 + arow] = make_float2(va.y, va.y);
        As2[(aq * 4 + 2) * 64 + arow] = make_float2(va.z, va.z);
        As2[(aq * 4 + 3) * 64 + arow] = make_float2(va.w, va.w);
        {
            const float v[16] = {vb0.x, vb0.y, vb0.z, vb0.w, vb1.x, vb1.y, vb1.z, vb1.w,
                                 vb2.x, vb2.y, vb2.z, vb2.w, vb3.x, vb3.y, vb3.z, vb3.w};
            #pragma unroll
            for (int j = 0; j < 16; j++) Bs[j * 256 + tid] = v[j];
        }
        __syncthreads();

        if (ko < 15) {
            const int kb = (ko + 1) * 16;
            va  = *(const float4*)(emb + (size_t)idx[arow] * E_ + kb + aq * 4);
            vb0 = *(const float4*)(Wm + (size_t)tid * E_ + kb + 0);
            vb1 = *(const float4*)(Wm + (size_t)tid * E_ + kb + 4);
            vb2 = *(const float4*)(Wm + (size_t)tid * E_ + kb + 8);
            vb3 = *(const float4*)(Wm + (size_t)tid * E_ + kb + 12);
        }

        #pragma unroll
        for (int k = 0; k < 16; k++) {
            u64t ap[4];
            #pragma unroll
            for (int i = 0; i < 4; i++)
                ap[i] = *(const u64t*)&As2[k * 64 + ty * 4 + i];
            #pragma unroll
            for (int q = 0; q < 4; q++) {
                const ulonglong2 bq = *(const ulonglong2*)&Bs[k * 256 + q * 64 + tx * 4];
                #pragma unroll
                for (int i = 0; i < 4; i++) {
                    acc[i][2 * q + 0] = ffma2(bq.x, ap[i], acc[i][2 * q + 0]);
                    acc[i][2 * q + 1] = ffma2(bq.y, ap[i], acc[i][2 * q + 1]);
                }
            }
        }
    }

    #pragma unroll
    for (int i = 0; i < 4; i++) {
        const int rg = r0 + ty * 4 + i;
        #pragma unroll
        for (int q = 0; q < 4; q++) {
            float4 o;
            o.x = f2lo(acc[i][2 * q + 0]); o.y = f2hi(acc[i][2 * q + 0]);
            o.z = f2lo(acc[i][2 * q + 1]); o.w = f2hi(acc[i][2 * q + 1]);
            __stcs((float4*)(g_xw + (size_t)rg * U_ + q * 64 + tx * 4), o);
        }
    }
}

// ---------------------------------------------------------------------------
// Phase 2: recurrence — EXACT R4 kernel (structure, protocol, ordering)
// with ONE change: h stored in padded 18-float chunks so the per-step
// LDS.64 h reads are conflict-free (R13-validated: L1% 47.5 -> 16.3).
// ---------------------------------------------------------------------------
__device__ __forceinline__ float reduce16(const float v[8], int ju) {
    const unsigned FM = 0xffffffffu;
    float w[4];
    const bool t3 = (ju & 8) != 0;
    #pragma unroll
    for (int a = 0; a < 4; a++) {
        const float keep = t3 ? v[a + 4] : v[a];
        const float send = t3 ? v[a] : v[a + 4];
        w[a] = keep + __shfl_xor_sync(FM, send, 8);
    }
    float x[2];
    const bool t2 = (ju & 4) != 0;
    #pragma unroll
    for (int a = 0; a < 2; a++) {
        const float keep = t2 ? w[a + 2] : w[a];
        const float send = t2 ? w[a] : w[a + 2];
        x[a] = keep + __shfl_xor_sync(FM, send, 4);
    }
    const bool t1 = (ju & 2) != 0;
    const float keep = t1 ? x[1] : x[0];
    const float send = t1 ? x[0] : x[1];
    float y = keep + __shfl_xor_sync(FM, send, 2);
    y += __shfl_xor_sync(FM, y, 1);
    return y;   // lane ju holds dot for a = ju>>1
}

__global__ void __cluster_dims__(2, 1, 1) __launch_bounds__(256, 1)
rnn_kernel(const float* __restrict__ Um,
           const float* __restrict__ W1, const float* __restrict__ b1v,
           const float* __restrict__ W2, const float* __restrict__ b2v,
           float* __restrict__ outp)
{
    __shared__ __align__(16) float hbuf[2][2][HB];      // [buf][b][chunk*18+slot]
    __shared__ __align__(8)  unsigned long long fullbar[2];
    __shared__ float hid[2][32];

    const int tid = threadIdx.x;
    unsigned rank;
    asm("mov.u32 %0, %%cluster_ctarank;" : "=r"(rank));
    const unsigned peer = rank ^ 1u;
    const int b0 = (blockIdx.x >> 1) * 2;
    const int b1i = b0 + 1;
    const int uhalf = (int)rank * 128;
    const int uu = tid >> 4;
    const int ju = tid & 15;

    // U chunk into registers: rows u = uhalf + uu*8 + a, cols ju*16..+15
    u64t Ur[8][8];
    #pragma unroll
    for (int a = 0; a < 8; a++) {
        const u64t* p = (const u64t*)(Um + (size_t)(uhalf + uu * 8 + a) * U_ + ju * 16);
        #pragma unroll
        for (int q = 0; q < 8; q++) Ur[a][q] = p[q];
    }

    for (int i = tid; i < 2 * 2 * HB; i += 256) ((float*)hbuf)[i] = 0.0f;

    const unsigned lh = (unsigned)__cvta_generic_to_shared(hbuf);
    const unsigned lb = (unsigned)__cvta_generic_to_shared(fullbar);
    unsigned rh, rb_;
    asm("mapa.shared::cluster.u32 %0, %1, %2;" : "=r"(rh)  : "r"(lh), "r"(peer));
    asm("mapa.shared::cluster.u32 %0, %1, %2;" : "=r"(rb_) : "r"(lb), "r"(peer));

    if (tid == 0) {
        mbar_init(lb + 0, 1);
        mbar_init(lb + 8, 1);
        mbar_expect(lb + 8, 2048);   // arm full[1] for phase 0 (peer's t=0 txs)
    }
    __syncthreads();
    cluster_sync_();                 // peer's init visible before any st.async

    const int u_g = uhalf + uu * 8 + (ju >> 1);
    const int po = (u_g >> 4) * CH + (u_g & 15);   // padded offset of u_g
    unsigned ph0 = 0, ph1 = 0;

    float cxw0 = __ldcs(g_xw + (size_t)b0  * U_ + u_g);
    float cxw1 = __ldcs(g_xw + (size_t)b1i * U_ + u_g);

    for (int t = 0; t < T_; t++) {
        const int rbuf = t & 1;
        const int wbuf = rbuf ^ 1;

        if (t > 0) {
            if (rbuf == 0) { mbar_wait(lb + 0, ph0); ph0 ^= 1u; }
            else           { mbar_wait(lb + 8, ph1); ph1 ^= 1u; }
        }
        if (tid == 0) mbar_expect(lb + rbuf * 8, 2048);  // re-arm for next phase

        // prefetch next step's xw (consumed next iteration)
        const int tn = (t + 1 < T_) ? t + 1 : t;
        const float nxw0 = __ldcs(g_xw + (size_t)tn * (B_ * U_) + b0  * U_ + u_g);
        const float nxw1 = __ldcs(g_xw + (size_t)tn * (B_ * U_) + b1i * U_ + u_g);

        u64t h0[8], h1[8];
        const u64t* hp0 = (const u64t*)&hbuf[rbuf][0][ju * CH];
        const u64t* hp1 = (const u64t*)&hbuf[rbuf][1][ju * CH];
        #pragma unroll
        for (int q = 0; q < 8; q++) { h0[q] = hp0[q]; h1[q] = hp1[q]; }

        float s0[8], s1[8];
        #pragma unroll
        for (int a = 0; a < 8; a++) {
            u64t ac0 = 0ull, ac1 = 0ull;
            #pragma unroll
            for (int q = 0; q < 8; q++) {
                ac0 = ffma2(Ur[a][q], h0[q], ac0);
                ac1 = ffma2(Ur[a][q], h1[q], ac1);
            }
            s0[a] = f2lo(ac0) + f2hi(ac0);
            s1[a] = f2lo(ac1) + f2hi(ac1);
        }

        const float d0 = reduce16(s0, ju);
        const float d1 = reduce16(s1, ju);
        const float v0 = tanh_fast(d0 + cxw0);
        const float v1 = tanh_fast(d1 + cxw1);

        const unsigned off0 = (unsigned)((wbuf * 2 + 0) * HB + po);
        const unsigned off1 = (unsigned)((wbuf * 2 + 1) * HB + po);
        hbuf[wbuf][0][po] = v0;
        hbuf[wbuf][1][po] = v1;
        st_async_f32(rh + off0 * 4u, v0, rb_ + (unsigned)wbuf * 8u);
        st_async_f32(rh + off1 * 4u, v1, rb_ + (unsigned)wbuf * 8u);

        __syncthreads();   // local-half visibility for next step's reads
        cxw0 = nxw0; cxw1 = nxw1;
    }

    // Final h is in buf 0; wait for peer's last txs, then local barrier.
    mbar_wait(lb + 0, ph0);
    __syncthreads();

    if (rank == 0) {
        if (tid < 32) {
            for (int bi = 0; bi < 2; bi++) {
                float acc = b1v[tid];
                const float* hr = hbuf[0][bi];
                #pragma unroll 8
                for (int j = 0; j < 256; j++)
                    acc = fmaf(hr[(j >> 4) * CH + (j & 15)],
                               __ldg(W1 + j * 32 + tid), acc);
                hid[bi][tid] = fmaxf(acc, 0.0f);
            }
        }
        __syncthreads();
        if (tid < 2) {
            float l0 = b2v[0], l1 = b2v[1];
            #pragma unroll
            for (int k = 0; k < 32; k++) {
                const float hv = hid[tid][k];
                l0 = fmaf(hv, __ldg(W2 + k * 2 + 0), l0);
                l1 = fmaf(hv, __ldg(W2 + k * 2 + 1), l1);
            }
            const float m = fmaxf(l0, l1);
            const float e0 = expf(l0 - m);
            const float e1 = expf(l1 - m);
            const float inv = 1.0f / (e0 + e1);
            outp[(b0 + tid) * 2 + 0] = e0 * inv;
            outp[(b0 + tid) * 2 + 1] = e1 * inv;
        }
    }
    cluster_sync_();   // no CTA exits while peer traffic could be in flight
}

// ---------------------------------------------------------------------------
extern "C" void kernel_launch(void* const* d_in, const int* in_sizes, int n_in,
                              void* d_out, int out_size)
{
    const int*   sent = (const int*)d_in[0];
    const float* emb  = (const float*)d_in[1];
    const float* Wm   = (const float*)d_in[2];
    const float* Um   = (const float*)d_in[3];
    const float* W1   = (const float*)d_in[4];
    const float* b1v  = (const float*)d_in[5];
    const float* W2   = (const float*)d_in[6];
    const float* b2v  = (const float*)d_in[7];
    float* outp = (float*)d_out;
    (void)in_sizes; (void)n_in; (void)out_size;

    xw_kernel<<<1024, 256>>>(sent, emb, Wm);
    rnn_kernel<<<128, 256>>>(Um, W1, b1v, W2, b2v, outp);
}

// round 15
// speedup vs baseline: 2.3279x; 1.0472x over previous
#include <cuda_runtime.h>
#include <cuda_bf16.h>

#define B_ 128
#define T_ 512
#define E_ 256
#define U_ 256

#define CH 36                // padded floats per 32-float h chunk (144B)
#define HB (8 * CH)          // 288 floats per (buf,batch)

typedef unsigned long long u64t;

// 64MB scratch: xw[t][b][u]
__device__ __align__(16) float g_xw[T_ * B_ * U_];

__device__ __forceinline__ u64t ffma2(u64t a, u64t b, u64t c) {
    u64t d;
    asm("fma.rn.f32x2 %0, %1, %2, %3;" : "=l"(d) : "l"(a), "l"(b), "l"(c));
    return d;
}
__device__ __forceinline__ float f2lo(u64t v) { return __uint_as_float((unsigned)(v & 0xffffffffull)); }
__device__ __forceinline__ float f2hi(u64t v) { return __uint_as_float((unsigned)(v >> 32)); }
__device__ __forceinline__ float tanh_fast(float x) {
    float ex = __expf(2.0f * x);
    return 1.0f - __fdividef(2.0f, ex + 1.0f);
}

// ---------------- mbarrier / cluster helpers (R4/R14 verbatim) ----------------
__device__ __forceinline__ void mbar_init(unsigned addr, unsigned cnt) {
    asm volatile("mbarrier.init.shared.b64 [%0], %1;" :: "r"(addr), "r"(cnt) : "memory");
}
__device__ __forceinline__ void mbar_expect(unsigned addr, unsigned bytes) {
    asm volatile("mbarrier.arrive.expect_tx.shared.b64 _, [%0], %1;"
                 :: "r"(addr), "r"(bytes) : "memory");
}
__device__ __forceinline__ void mbar_wait(unsigned addr, unsigned parity) {
    unsigned done;
    asm volatile(
        "{\n\t.reg .pred p;\n\t"
        "mbarrier.try_wait.parity.acquire.cta.shared::cta.b64 p, [%1], %2;\n\t"
        "selp.b32 %0, 1, 0, p;\n\t}"
        : "=r"(done) : "r"(addr), "r"(parity) : "memory");
    if (!done) {
        asm volatile(
            "{\n\t.reg .pred P1;\n\t"
            "W_%=:\n\t"
            "mbarrier.try_wait.parity.acquire.cta.shared::cta.b64 P1, [%0], %1, 0x989680;\n\t"
            "@P1 bra D_%=;\n\t"
            "bra W_%=;\n\t"
            "D_%=:\n\t}"
            :: "r"(addr), "r"(parity) : "memory");
    }
}
__device__ __forceinline__ void st_async_f32(unsigned raddr, float v, unsigned rbar) {
    asm volatile("st.async.shared::cluster.mbarrier::complete_tx::bytes.b32 [%0], %1, [%2];"
                 :: "r"(raddr), "r"(__float_as_uint(v)), "r"(rbar) : "memory");
}
__device__ __forceinline__ void cluster_sync_() {
    asm volatile("barrier.cluster.arrive.aligned;" ::: "memory");
    asm volatile("barrier.cluster.wait.aligned;" ::: "memory");
}

// ---------------------------------------------------------------------------
// Phase 1: xw[t][b][u] = sum_e emb[sentence[b][t]][e] * W[u][e]  (unchanged)
// ---------------------------------------------------------------------------
__global__ void __launch_bounds__(256)
xw_kernel(const int* __restrict__ sent, const float* __restrict__ emb,
          const float* __restrict__ Wm)
{
    __shared__ __align__(16) float2 As2[16 * 64];
    __shared__ __align__(16) float  Bs[16 * 256];
    __shared__ int idx[64];

    const int tid = threadIdx.x;
    const int r0 = blockIdx.x * 64;
    const int t  = r0 >> 7;
    const int b0 = r0 & 127;

    if (tid < 64) idx[tid] = sent[(b0 + tid) * T_ + t];
    __syncthreads();

    const int tx = tid & 15;
    const int ty = tid >> 4;
    const int arow = tid >> 2;
    const int aq = tid & 3;

    u64t acc[4][8];
    #pragma unroll
    for (int i = 0; i < 4; i++)
        #pragma unroll
        for (int p = 0; p < 8; p++) acc[i][p] = 0ull;

    float4 va = *(const float4*)(emb + (size_t)idx[arow] * E_ + aq * 4);
    float4 vb0 = *(const float4*)(Wm + (size_t)tid * E_ + 0);
    float4 vb1 = *(const float4*)(Wm + (size_t)tid * E_ + 4);
    float4 vb2 = *(const float4*)(Wm + (size_t)tid * E_ + 8);
    float4 vb3 = *(const float4*)(Wm + (size_t)tid * E_ + 12);

    for (int ko = 0; ko < 16; ko++) {
        if (ko > 0) __syncthreads();

        As2[(aq * 4 + 0) * 64 + arow] = make_float2(va.x, va.x);
        As2[(aq * 4 + 1) * 64 + arow] = make_float2(va.y, va.y);
        As2[(aq * 4 + 2) * 64 + arow] = make_float2(va.z, va.z);
        As2[(aq * 4 + 3) * 64 + arow] = make_float2(va.w, va.w);
        {
            const float v[16] = {vb0.x, vb0.y, vb0.z, vb0.w, vb1.x, vb1.y, vb1.z, vb1.w,
                                 vb2.x, vb2.y, vb2.z, vb2.w, vb3.x, vb3.y, vb3.z, vb3.w};
            #pragma unroll
            for (int j = 0; j < 16; j++) Bs[j * 256 + tid] = v[j];
        }
        __syncthreads();

        if (ko < 15) {
            const int kb = (ko + 1) * 16;
            va  = *(const float4*)(emb + (size_t)idx[arow] * E_ + kb + aq * 4);
            vb0 = *(const float4*)(Wm + (size_t)tid * E_ + kb + 0);
            vb1 = *(const float4*)(Wm + (size_t)tid * E_ + kb + 4);
            vb2 = *(const float4*)(Wm + (size_t)tid * E_ + kb + 8);
            vb3 = *(const float4*)(Wm + (size_t)tid * E_ + kb + 12);
        }

        #pragma unroll
        for (int k = 0; k < 16; k++) {
            u64t ap[4];
            #pragma unroll
            for (int i = 0; i < 4; i++)
                ap[i] = *(const u64t*)&As2[k * 64 + ty * 4 + i];
            #pragma unroll
            for (int q = 0; q < 4; q++) {
                const ulonglong2 bq = *(const ulonglong2*)&Bs[k * 256 + q * 64 + tx * 4];
                #pragma unroll
                for (int i = 0; i < 4; i++) {
                    acc[i][2 * q + 0] = ffma2(bq.x, ap[i], acc[i][2 * q + 0]);
                    acc[i][2 * q + 1] = ffma2(bq.y, ap[i], acc[i][2 * q + 1]);
                }
            }
        }
    }

    #pragma unroll
    for (int i = 0; i < 4; i++) {
        const int rg = r0 + ty * 4 + i;
        #pragma unroll
        for (int q = 0; q < 4; q++) {
            float4 o;
            o.x = f2lo(acc[i][2 * q + 0]); o.y = f2hi(acc[i][2 * q + 0]);
            o.z = f2lo(acc[i][2 * q + 1]); o.w = f2hi(acc[i][2 * q + 1]);
            __stcs((float4*)(g_xw + (size_t)rg * U_ + q * 64 + tx * 4), o);
        }
    }
}

// ---------------------------------------------------------------------------
// Phase 2: recurrence — R14 protocol verbatim; ONE change: 4-row x 32-col
// tiles (thread uu=tid>>3 owns rows uhalf+uu*4+{0..3}, cols ju*32..+31,
// ju=tid&7) with 36-float padded h chunks (conflict-free LDS.128).
// Reduce: 8 values over 8 lanes, 7 shfl depth 3; lane ju finalizes ONE
// (batch=ju>>2, row=ju&3): 1 tanh, 1 STS, 1 st.async (tx 1024).
// ---------------------------------------------------------------------------
__global__ void __cluster_dims__(2, 1, 1) __launch_bounds__(256, 1)
rnn_kernel(const float* __restrict__ Um,
           const float* __restrict__ W1, const float* __restrict__ b1v,
           const float* __restrict__ W2, const float* __restrict__ b2v,
           float* __restrict__ outp)
{
    __shared__ __align__(16) float hbuf[2][2][HB];      // [buf][b][chunk*36+slot]
    __shared__ __align__(8)  unsigned long long fullbar[2];
    __shared__ float hid[2][32];

    const int tid = threadIdx.x;
    unsigned rank;
    asm("mov.u32 %0, %%cluster_ctarank;" : "=r"(rank));
    const unsigned peer = rank ^ 1u;
    const int b0 = (blockIdx.x >> 1) * 2;
    const int uhalf = (int)rank * 128;
    const int uu = tid >> 3;             // 0..31 -> 4 rows each
    const int ju = tid & 7;              // 32-col chunk

    // U rows uhalf+uu*4+a, cols ju*32..+31 -> Ur[4][16] (64 u64 = 128 regs)
    u64t Ur[4][16];
    #pragma unroll
    for (int a = 0; a < 4; a++) {
        const u64t* p = (const u64t*)(Um + (size_t)(uhalf + uu * 4 + a) * U_ + ju * 32);
        #pragma unroll
        for (int q = 0; q < 16; q++) Ur[a][q] = p[q];
    }

    for (int i = tid; i < 2 * 2 * HB; i += 256) ((float*)hbuf)[i] = 0.0f;

    const unsigned lh = (unsigned)__cvta_generic_to_shared(hbuf);
    const unsigned lb = (unsigned)__cvta_generic_to_shared(fullbar);
    unsigned rh, rb_;
    asm("mapa.shared::cluster.u32 %0, %1, %2;" : "=r"(rh)  : "r"(lh), "r"(peer));
    asm("mapa.shared::cluster.u32 %0, %1, %2;" : "=r"(rb_) : "r"(lb), "r"(peer));

    if (tid == 0) {
        mbar_init(lb + 0, 1);
        mbar_init(lb + 8, 1);
        mbar_expect(lb + 8, 1024);   // arm full[1] for phase 0 (peer's t=0 txs)
    }
    __syncthreads();
    cluster_sync_();                 // peer's init visible before any st.async

    // finalize role: batch = ju>>2, row = uhalf + uu*4 + (ju&3)
    const int batch = ju >> 2;
    const int u_fin = uhalf + uu * 4 + (ju & 3);
    const int po = (u_fin >> 5) * CH + (u_fin & 31);   // padded offset
    unsigned ph0 = 0, ph1 = 0;

    float cxw = __ldcs(g_xw + (size_t)(b0 + batch) * U_ + u_fin);
    float hval = 0.0f;

    for (int t = 0; t < T_; t++) {
        const int rbuf = t & 1;
        const int wbuf = rbuf ^ 1;

        if (t > 0) {
            if (rbuf == 0) { mbar_wait(lb + 0, ph0); ph0 ^= 1u; }
            else           { mbar_wait(lb + 8, ph1); ph1 ^= 1u; }
        }
        if (tid == 0) mbar_expect(lb + rbuf * 8, 1024);  // re-arm for next phase

        // prefetch next step's xw (consumed next iteration)
        const int tn = (t + 1 < T_) ? t + 1 : t;
        const float nxw = __ldcs(g_xw + (size_t)tn * (B_ * U_) +
                                 (size_t)(b0 + batch) * U_ + u_fin);

        // partial dots: 2 batches x 4 rows over my 32-col chunk
        float v[8];
        #pragma unroll
        for (int B2 = 0; B2 < 2; B2++) {
            u64t hv[16];
            const ulonglong2* hp = (const ulonglong2*)&hbuf[rbuf][B2][ju * CH];
            #pragma unroll
            for (int k = 0; k < 8; k++) {
                const ulonglong2 h2 = hp[k];
                hv[2 * k + 0] = h2.x;
                hv[2 * k + 1] = h2.y;
            }
            #pragma unroll
            for (int a = 0; a < 4; a++) {
                u64t ac0 = 0ull, ac1 = 0ull;
                #pragma unroll
                for (int q = 0; q < 8; q++) {
                    ac0 = ffma2(Ur[a][2 * q + 0], hv[2 * q + 0], ac0);
                    ac1 = ffma2(Ur[a][2 * q + 1], hv[2 * q + 1], ac1);
                }
                const float lo = f2lo(ac0) + f2hi(ac0);
                const float hi2 = f2lo(ac1) + f2hi(ac1);
                v[B2 * 4 + a] = lo + hi2;
            }
        }

        // reduce-scatter 8 values over 8 lanes (xor 4,2,1): lane ju -> v[ju]
        float w[4];
        {
            const bool hi = (ju & 4) != 0;
            #pragma unroll
            for (int a = 0; a < 4; a++) {
                const float keep = hi ? v[a + 4] : v[a];
                const float send = hi ? v[a] : v[a + 4];
                w[a] = keep + __shfl_xor_sync(0xffffffffu, send, 4);
            }
        }
        float x[2];
        {
            const bool hi = (ju & 2) != 0;
            #pragma unroll
            for (int a = 0; a < 2; a++) {
                const float keep = hi ? w[a + 2] : w[a];
                const float send = hi ? w[a] : w[a + 2];
                x[a] = keep + __shfl_xor_sync(0xffffffffu, send, 2);
            }
        }
        float d;
        {
            const bool hi = (ju & 1) != 0;
            const float keep = hi ? x[1] : x[0];
            const float send = hi ? x[0] : x[1];
            d = keep + __shfl_xor_sync(0xffffffffu, send, 1);
        }

        hval = tanh_fast(d + cxw);
        const unsigned off = (unsigned)((wbuf * 2 + batch) * HB + po);
        hbuf[wbuf][batch][po] = hval;
        st_async_f32(rh + off * 4u, hval, rb_ + (unsigned)wbuf * 8u);

        __syncthreads();   // local-half visibility for next step's reads
        cxw = nxw;
    }

    // Final h is in buf 0; wait for peer's last txs, then local barrier.
    mbar_wait(lb + 0, ph0);
    __syncthreads();

    if (rank == 0) {
        if (tid < 32) {
            for (int bi = 0; bi < 2; bi++) {
                float acc = b1v[tid];
                const float* hr = hbuf[0][bi];
                #pragma unroll 8
                for (int j = 0; j < 256; j++)
                    acc = fmaf(hr[(j >> 5) * CH + (j & 31)],
                               __ldg(W1 + j * 32 + tid), acc);
                hid[bi][tid] = fmaxf(acc, 0.0f);
            }
        }
        __syncthreads();
        if (tid < 2) {
            float l0 = b2v[0], l1 = b2v[1];
            #pragma unroll
            for (int k = 0; k < 32; k++) {
                const float hv2 = hid[tid][k];
                l0 = fmaf(hv2, __ldg(W2 + k * 2 + 0), l0);
                l1 = fmaf(hv2, __ldg(W2 + k * 2 + 1), l1);
            }
            const float m = fmaxf(l0, l1);
            const float e0 = expf(l0 - m);
            const float e1 = expf(l1 - m);
            const float inv = 1.0f / (e0 + e1);
            outp[(b0 + tid) * 2 + 0] = e0 * inv;
            outp[(b0 + tid) * 2 + 1] = e1 * inv;
        }
    }
    cluster_sync_();   // no CTA exits while peer traffic could be in flight
}

// ---------------------------------------------------------------------------
extern "C" void kernel_launch(void* const* d_in, const int* in_sizes, int n_in,
                              void* d_out, int out_size)
{
    const int*   sent = (const int*)d_in[0];
    const float* emb  = (const float*)d_in[1];
    const float* Wm   = (const float*)d_in[2];
    const float* Um   = (const float*)d_in[3];
    const float* W1   = (const float*)d_in[4];
    const float* b1v  = (const float*)d_in[5];
    const float* W2   = (const float*)d_in[6];
    const float* b2v  = (const float*)d_in[7];
    float* outp = (float*)d_out;
    (void)in_sizes; (void)n_in; (void)out_size;

    xw_kernel<<<1024, 256>>>(sent, emb, Wm);
    rnn_kernel<<<128, 256>>>(Um, W1, b1v, W2, b2v, outp);
}